// round 5
// baseline (speedup 1.0000x reference)
#include <cuda_runtime.h>

#define N_NODES 100000
#define N_EDGES 1600000
#define NFEAT   128
#define NHID    64
#define CAP     64              // padded bucket capacity per row (max degree ~45)
#define GEMM_BLOCKS 391         // 391*256 = 100096 rows
#define BUILD_BLOCKS 6250       // 6250*256 = 1.6M edges

// ---- scratch (__device__ globals: zero-initialized at module load) ---------
__device__ float              g_support[N_NODES * NHID];     // 25.6 MB
__device__ int                g_cnt[N_NODES];                 // cursor; re-zeroed by reduce
__device__ unsigned long long g_edges[N_NODES * CAP];         // 51.2 MB padded buckets

// ---------------------------------------------------------------------------
// JAX partitionable threefry2x32, key (0,42), count (0, i): returns out0^out1
// ---------------------------------------------------------------------------
__device__ __forceinline__ unsigned tf_hash(unsigned i) {
    const unsigned ks0 = 0u, ks1 = 42u, ks2 = 0x1BD11BF0u;  // 0 ^ 42 ^ 0x1BD11BDA
    unsigned x0 = ks0;        // counts_hi = 0
    unsigned x1 = i + ks1;    // counts_lo = i
#define TFR(r) { x0 += x1; x1 = __funnelshift_l(x1, x1, (r)); x1 ^= x0; }
    TFR(13) TFR(15) TFR(26) TFR(6)   x0 += ks1; x1 += ks2 + 1u;
    TFR(17) TFR(29) TFR(16) TFR(24)  x0 += ks2; x1 += ks0 + 2u;
    TFR(13) TFR(15) TFR(26) TFR(6)   x0 += ks0; x1 += ks1 + 3u;
    TFR(17) TFR(29) TFR(16) TFR(24)  x0 += ks1; x1 += ks2 + 4u;
    TFR(13) TFR(15) TFR(26) TFR(6)   x0 += ks2; x1 += ks0 + 5u;
#undef TFR
    return x0 ^ x1;
}

// ---------------------------------------------------------------------------
// FUSED kernel: blocks [0, GEMM_BLOCKS) run the GEMM tile; the rest build the
// padded edge buckets. GEMM blocks are first so they co-reside with build
// blocks from wave 1: FMA pipe (gemm) and L2 atomics (build) overlap.
// ---------------------------------------------------------------------------
__global__ __launch_bounds__(256) void fused_kernel(const float* __restrict__ x,
                                                    const float* __restrict__ W,
                                                    const int*   __restrict__ erow,
                                                    const int*   __restrict__ ecol,
                                                    const float* __restrict__ ev) {
    __shared__ float Xs[256][33];   // 33.8 KB
    __shared__ float Ws[32][64];    //  8 KB   (total 41.98 KB < 48 KB default)

    if (blockIdx.x >= GEMM_BLOCKS) {
        // ---------------- build branch ----------------
        int e = (blockIdx.x - GEMM_BLOCKS) * 256 + threadIdx.x;
        int   r = erow[e];
        int   c = ecol[e];
        float v = ev[e];
        int pos = atomicAdd(&g_cnt[r], 1);
        if (pos < CAP)   // statistically impossible to overflow; guard vs corruption
            g_edges[r * CAP + pos] =
                ((unsigned long long)__float_as_uint(v) << 32) | (unsigned)c;
        return;
    }

    // ---------------- gemm branch ----------------
    const int tid  = threadIdx.x;
    const int lane = tid & 31;
    const int tx   = tid >> 5;
    const int bm   = blockIdx.x * 256;

    float acc[8][8];
#pragma unroll
    for (int j = 0; j < 8; j++)
#pragma unroll
        for (int n = 0; n < 8; n++) acc[j][n] = 0.f;

    for (int kc = 0; kc < 4; kc++) {
#pragma unroll
        for (int i = 0; i < 8; i++) {
            int fi  = tid + i * 256;
            int row = fi >> 3;
            int kq  = fi & 7;
            int grow = bm + row;
            float4 v = make_float4(0.f, 0.f, 0.f, 0.f);
            if (grow < N_NODES)
                v = reinterpret_cast<const float4*>(x)[grow * 32 + kc * 8 + kq];
            Xs[row][kq * 4 + 0] = v.x;
            Xs[row][kq * 4 + 1] = v.y;
            Xs[row][kq * 4 + 2] = v.z;
            Xs[row][kq * 4 + 3] = v.w;
        }
#pragma unroll
        for (int i = 0; i < 2; i++) {
            int fi = tid + i * 256;
            int kk = fi >> 4;
            int nq = fi & 15;
            reinterpret_cast<float4*>(&Ws[kk][nq * 4])[0] =
                reinterpret_cast<const float4*>(W)[(kc * 32 + kk) * 16 + nq];
        }
        __syncthreads();

#pragma unroll 4
        for (int k = 0; k < 32; k++) {
            float4 b0 = *reinterpret_cast<const float4*>(&Ws[k][tx * 8]);
            float4 b1 = *reinterpret_cast<const float4*>(&Ws[k][tx * 8 + 4]);
#pragma unroll
            for (int j = 0; j < 8; j++) {
                float a = Xs[lane + 32 * j][k];
                acc[j][0] += a * b0.x; acc[j][1] += a * b0.y;
                acc[j][2] += a * b0.z; acc[j][3] += a * b0.w;
                acc[j][4] += a * b1.x; acc[j][5] += a * b1.y;
                acc[j][6] += a * b1.z; acc[j][7] += a * b1.w;
            }
        }
        __syncthreads();
    }

#pragma unroll
    for (int j = 0; j < 8; j++) {
        int r = bm + lane + 32 * j;
        if (r < N_NODES) {
            float4* dst = reinterpret_cast<float4*>(&g_support[r * 64 + tx * 8]);
            dst[0] = make_float4(acc[j][0], acc[j][1], acc[j][2], acc[j][3]);
            dst[1] = make_float4(acc[j][4], acc[j][5], acc[j][6], acc[j][7]);
        }
    }
}

// ---------------------------------------------------------------------------
// Gather-reduce + fused epilogue: one warp per row.
// Edge words fetched with ONE coalesced 256B load (lane = slot), shfl-broadcast.
// 8-wide gather rounds with 4 independent accumulator pairs -> MLP ~8.
// Also re-zeroes g_cnt[row] so the next call starts clean (no memset node).
// ---------------------------------------------------------------------------
__global__ __launch_bounds__(256) void reduce_kernel(float* __restrict__ out,
                                                     const float* __restrict__ bias) {
    int lane = threadIdx.x & 31;
    int wid  = threadIdx.x >> 5;
    int row  = blockIdx.x * 8 + wid;          // grid 12500 -> exact

    int deg = g_cnt[row];
    if (lane == 0) g_cnt[row] = 0;            // reset cursor for next call
    if (deg > CAP) deg = CAP;
    const unsigned long long* ebase = g_edges + (size_t)row * CAP;

    const float2* sup = reinterpret_cast<const float2*>(g_support);
    unsigned long long ew_l = ebase[lane];    // one 256B coalesced load
    int nb = deg < 32 ? deg : 32;

    float ax0 = 0.f, ay0 = 0.f, ax1 = 0.f, ay1 = 0.f;
    float ax2 = 0.f, ay2 = 0.f, ax3 = 0.f, ay3 = 0.f;

    int j = 0;
    for (; j + 8 <= nb; j += 8) {
        unsigned long long e0 = __shfl_sync(0xFFFFFFFFu, ew_l, j + 0);
        unsigned long long e1 = __shfl_sync(0xFFFFFFFFu, ew_l, j + 1);
        unsigned long long e2 = __shfl_sync(0xFFFFFFFFu, ew_l, j + 2);
        unsigned long long e3 = __shfl_sync(0xFFFFFFFFu, ew_l, j + 3);
        unsigned long long e4 = __shfl_sync(0xFFFFFFFFu, ew_l, j + 4);
        unsigned long long e5 = __shfl_sync(0xFFFFFFFFu, ew_l, j + 5);
        unsigned long long e6 = __shfl_sync(0xFFFFFFFFu, ew_l, j + 6);
        unsigned long long e7 = __shfl_sync(0xFFFFFFFFu, ew_l, j + 7);
        float2 s0 = sup[(unsigned)e0 * 32u + lane];
        float2 s1 = sup[(unsigned)e1 * 32u + lane];
        float2 s2 = sup[(unsigned)e2 * 32u + lane];
        float2 s3 = sup[(unsigned)e3 * 32u + lane];
        float2 s4 = sup[(unsigned)e4 * 32u + lane];
        float2 s5 = sup[(unsigned)e5 * 32u + lane];
        float2 s6 = sup[(unsigned)e6 * 32u + lane];
        float2 s7 = sup[(unsigned)e7 * 32u + lane];
        float v0 = __uint_as_float((unsigned)(e0 >> 32));
        float v1 = __uint_as_float((unsigned)(e1 >> 32));
        float v2 = __uint_as_float((unsigned)(e2 >> 32));
        float v3 = __uint_as_float((unsigned)(e3 >> 32));
        float v4 = __uint_as_float((unsigned)(e4 >> 32));
        float v5 = __uint_as_float((unsigned)(e5 >> 32));
        float v6 = __uint_as_float((unsigned)(e6 >> 32));
        float v7 = __uint_as_float((unsigned)(e7 >> 32));
        ax0 += v0 * s0.x; ay0 += v0 * s0.y;
        ax1 += v1 * s1.x; ay1 += v1 * s1.y;
        ax2 += v2 * s2.x; ay2 += v2 * s2.y;
        ax3 += v3 * s3.x; ay3 += v3 * s3.y;
        ax0 += v4 * s4.x; ay0 += v4 * s4.y;
        ax1 += v5 * s5.x; ay1 += v5 * s5.y;
        ax2 += v6 * s6.x; ay2 += v6 * s6.y;
        ax3 += v7 * s7.x; ay3 += v7 * s7.y;
    }
    for (; j < nb; j++) {
        unsigned long long ew = __shfl_sync(0xFFFFFFFFu, ew_l, j);
        float2 s = sup[(unsigned)ew * 32u + lane];
        float  v = __uint_as_float((unsigned)(ew >> 32));
        ax0 += v * s.x; ay0 += v * s.y;
    }
    if (deg > 32) {   // rare tail (P ~ 1e-4 of rows)
        unsigned long long ew_h = ebase[32 + lane];
        int nb2 = deg - 32;
        for (int t = 0; t < nb2; t++) {
            unsigned long long ew = __shfl_sync(0xFFFFFFFFu, ew_h, t);
            float2 s = sup[(unsigned)ew * 32u + lane];
            float  v = __uint_as_float((unsigned)(ew >> 32));
            ax0 += v * s.x; ay0 += v * s.y;
        }
    }

    float ax = (ax0 + ax1) + (ax2 + ax3);
    float ay = (ay0 + ay1) + (ay2 + ay3);

    float2 bv = reinterpret_cast<const float2*>(bias)[lane];
    float h0 = ax + bv.x, h1 = ay + bv.y;
    h0 = h0 > 0.f ? 2.f * h0 : 0.f;
    h1 = h1 > 0.f ? 2.f * h1 : 0.f;

    unsigned i0 = (unsigned)row * 64u + (unsigned)lane * 2u;
    unsigned m0 = tf_hash(i0);
    unsigned m1 = tf_hash(i0 + 1u);

    float2 o;
    o.x = (m0 & 0x80000000u) ? 0.f : h0;
    o.y = (m1 & 0x80000000u) ? 0.f : h1;
    reinterpret_cast<float2*>(out)[(unsigned)row * 32u + lane] = o;
}

// ---------------------------------------------------------------------------
extern "C" void kernel_launch(void* const* d_in, const int* in_sizes, int n_in,
                              void* d_out, int out_size) {
    const float* x    = (const float*)d_in[0];
    const int*   erow = (const int*)  d_in[1];
    const int*   ecol = (const int*)  d_in[2];
    const float* ev   = (const float*)d_in[3];
    const float* W    = (const float*)d_in[4];
    const float* b    = (const float*)d_in[5];
    float* out = (float*)d_out;

    fused_kernel<<<GEMM_BLOCKS + BUILD_BLOCKS, 256>>>(x, W, erow, ecol, ev);
    reduce_kernel<<<12500, 256>>>(out, b);
}

// round 6
// speedup vs baseline: 1.5792x; 1.5792x over previous
#include <cuda_runtime.h>

#define N_NODES 100000
#define N_EDGES 1600000
#define NFEAT   128
#define NHID    64
#define CAP     64              // padded bucket capacity per row (max degree ~45)

// ---- scratch (__device__ globals: zero-initialized at module load) ---------
__device__ float              g_support[N_NODES * NHID];     // 25.6 MB
__device__ int                g_cnt[N_NODES];                 // cursor; re-zeroed by reduce
__device__ unsigned long long g_edges[N_NODES * CAP];         // 51.2 MB padded buckets

// ---------------------------------------------------------------------------
// JAX partitionable threefry2x32, key (0,42), count (0, i): returns out0^out1
// ---------------------------------------------------------------------------
__device__ __forceinline__ unsigned tf_hash(unsigned i) {
    const unsigned ks0 = 0u, ks1 = 42u, ks2 = 0x1BD11BF0u;  // 0 ^ 42 ^ 0x1BD11BDA
    unsigned x0 = ks0;        // counts_hi = 0
    unsigned x1 = i + ks1;    // counts_lo = i
#define TFR(r) { x0 += x1; x1 = __funnelshift_l(x1, x1, (r)); x1 ^= x0; }
    TFR(13) TFR(15) TFR(26) TFR(6)   x0 += ks1; x1 += ks2 + 1u;
    TFR(17) TFR(29) TFR(16) TFR(24)  x0 += ks2; x1 += ks0 + 2u;
    TFR(13) TFR(15) TFR(26) TFR(6)   x0 += ks0; x1 += ks1 + 3u;
    TFR(17) TFR(29) TFR(16) TFR(24)  x0 += ks1; x1 += ks2 + 4u;
    TFR(13) TFR(15) TFR(26) TFR(6)   x0 += ks2; x1 += ks0 + 5u;
#undef TFR
    return x0 ^ x1;
}

// ---------------------------------------------------------------------------
// Bucket build: one pass, no scan. idx = row*CAP + atomic cursor.
// Runs FIRST so its 70MB of L2 traffic is flushed by gemm before reduce runs.
// ---------------------------------------------------------------------------
__global__ __launch_bounds__(256) void build_kernel(const int*   __restrict__ erow,
                                                    const int*   __restrict__ ecol,
                                                    const float* __restrict__ ev) {
    int e = blockIdx.x * 256 + threadIdx.x;
    if (e >= N_EDGES) return;
    int   r = erow[e];
    int   c = ecol[e];
    float v = ev[e];
    int pos = atomicAdd(&g_cnt[r], 1);
    if (pos < CAP)   // statistically impossible to overflow; guard vs corruption
        g_edges[r * CAP + pos] =
            ((unsigned long long)__float_as_uint(v) << 32) | (unsigned)c;
}

// ---------------------------------------------------------------------------
// GEMM: support[100000,64] = x[100000,128] @ W[128,64]
// Tile 256 rows x 64 cols, 256 threads, K-chunks of 32; 8x8 per thread.
// Runs LAST before reduce: support freshest in L2.
// ---------------------------------------------------------------------------
__global__ __launch_bounds__(256, 2) void gemm_kernel(const float* __restrict__ x,
                                                      const float* __restrict__ W) {
    __shared__ float Xs[256][33];
    __shared__ float Ws[32][64];
    const int tid  = threadIdx.x;
    const int lane = tid & 31;
    const int tx   = tid >> 5;
    const int bm   = blockIdx.x * 256;

    float acc[8][8];
#pragma unroll
    for (int j = 0; j < 8; j++)
#pragma unroll
        for (int n = 0; n < 8; n++) acc[j][n] = 0.f;

    for (int kc = 0; kc < 4; kc++) {
#pragma unroll
        for (int i = 0; i < 8; i++) {
            int fi  = tid + i * 256;
            int row = fi >> 3;
            int kq  = fi & 7;
            int grow = bm + row;
            float4 v = make_float4(0.f, 0.f, 0.f, 0.f);
            if (grow < N_NODES)
                v = reinterpret_cast<const float4*>(x)[grow * 32 + kc * 8 + kq];
            Xs[row][kq * 4 + 0] = v.x;
            Xs[row][kq * 4 + 1] = v.y;
            Xs[row][kq * 4 + 2] = v.z;
            Xs[row][kq * 4 + 3] = v.w;
        }
#pragma unroll
        for (int i = 0; i < 2; i++) {
            int fi = tid + i * 256;
            int kk = fi >> 4;
            int nq = fi & 15;
            reinterpret_cast<float4*>(&Ws[kk][nq * 4])[0] =
                reinterpret_cast<const float4*>(W)[(kc * 32 + kk) * 16 + nq];
        }
        __syncthreads();

#pragma unroll 4
        for (int k = 0; k < 32; k++) {
            float4 b0 = *reinterpret_cast<const float4*>(&Ws[k][tx * 8]);
            float4 b1 = *reinterpret_cast<const float4*>(&Ws[k][tx * 8 + 4]);
#pragma unroll
            for (int j = 0; j < 8; j++) {
                float a = Xs[lane + 32 * j][k];
                acc[j][0] += a * b0.x; acc[j][1] += a * b0.y;
                acc[j][2] += a * b0.z; acc[j][3] += a * b0.w;
                acc[j][4] += a * b1.x; acc[j][5] += a * b1.y;
                acc[j][6] += a * b1.z; acc[j][7] += a * b1.w;
            }
        }
        __syncthreads();
    }

#pragma unroll
    for (int j = 0; j < 8; j++) {
        int r = bm + lane + 32 * j;
        if (r < N_NODES) {
            float4* dst = reinterpret_cast<float4*>(&g_support[r * 64 + tx * 8]);
            dst[0] = make_float4(acc[j][0], acc[j][1], acc[j][2], acc[j][3]);
            dst[1] = make_float4(acc[j][4], acc[j][5], acc[j][6], acc[j][7]);
        }
    }
}

// ---------------------------------------------------------------------------
// Gather-reduce + fused epilogue: TWO rows per warp (independent edge streams
// interleaved -> ~8 outstanding L2 gathers). Proven unroll-4 shfl pattern.
// Resets g_cnt for the next call (replaces the memset node).
// ---------------------------------------------------------------------------
__global__ __launch_bounds__(256) void reduce_kernel(float* __restrict__ out,
                                                     const float* __restrict__ bias) {
    int lane = threadIdx.x & 31;
    int wid  = threadIdx.x >> 5;
    int r0   = blockIdx.x * 16 + wid * 2;     // grid 6250 -> rows exact
    int r1   = r0 + 1;

    int deg0 = g_cnt[r0];
    int deg1 = g_cnt[r1];
    if (lane == 0) { g_cnt[r0] = 0; g_cnt[r1] = 0; }   // reset for next call
    if (deg0 > CAP) deg0 = CAP;
    if (deg1 > CAP) deg1 = CAP;

    const unsigned long long* eb0 = g_edges + (size_t)r0 * CAP;
    const unsigned long long* eb1 = g_edges + (size_t)r1 * CAP;
    unsigned long long ew0 = eb0[lane];       // one 256B coalesced load each
    unsigned long long ew1 = eb1[lane];

    const float2* sup = reinterpret_cast<const float2*>(g_support);
    float ax = 0.f, ay = 0.f;                 // row0 accum
    float bx = 0.f, by = 0.f;                 // row1 accum

    int nb0 = deg0 < 32 ? deg0 : 32;
    int nb1 = deg1 < 32 ? deg1 : 32;
    int nmin = nb0 < nb1 ? nb0 : nb1;

    int j = 0;
#pragma unroll 4
    for (; j < nmin; j++) {                   // both rows: 2 gathers/iter, x4 unroll
        unsigned long long e0 = __shfl_sync(0xFFFFFFFFu, ew0, j);
        unsigned long long e1 = __shfl_sync(0xFFFFFFFFu, ew1, j);
        float2 s0 = sup[(unsigned)e0 * 32u + lane];
        float2 s1 = sup[(unsigned)e1 * 32u + lane];
        float v0 = __uint_as_float((unsigned)(e0 >> 32));
        float v1 = __uint_as_float((unsigned)(e1 >> 32));
        ax += v0 * s0.x; ay += v0 * s0.y;
        bx += v1 * s1.x; by += v1 * s1.y;
    }
#pragma unroll 4
    for (int t = j; t < nb0; t++) {           // row0 remainder
        unsigned long long e0 = __shfl_sync(0xFFFFFFFFu, ew0, t);
        float2 s0 = sup[(unsigned)e0 * 32u + lane];
        float v0 = __uint_as_float((unsigned)(e0 >> 32));
        ax += v0 * s0.x; ay += v0 * s0.y;
    }
#pragma unroll 4
    for (int t = j; t < nb1; t++) {           // row1 remainder
        unsigned long long e1 = __shfl_sync(0xFFFFFFFFu, ew1, t);
        float2 s1 = sup[(unsigned)e1 * 32u + lane];
        float v1 = __uint_as_float((unsigned)(e1 >> 32));
        bx += v1 * s1.x; by += v1 * s1.y;
    }
    if (deg0 > 32) {                          // rare tails (P ~ 1e-4)
        unsigned long long ewh = eb0[32 + lane];
        for (int t = 0; t < deg0 - 32; t++) {
            unsigned long long e = __shfl_sync(0xFFFFFFFFu, ewh, t);
            float2 s = sup[(unsigned)e * 32u + lane];
            float v = __uint_as_float((unsigned)(e >> 32));
            ax += v * s.x; ay += v * s.y;
        }
    }
    if (deg1 > 32) {
        unsigned long long ewh = eb1[32 + lane];
        for (int t = 0; t < deg1 - 32; t++) {
            unsigned long long e = __shfl_sync(0xFFFFFFFFu, ewh, t);
            float2 s = sup[(unsigned)e * 32u + lane];
            float v = __uint_as_float((unsigned)(e >> 32));
            bx += v * s.x; by += v * s.y;
        }
    }

    float2 bv = reinterpret_cast<const float2*>(bias)[lane];

    float h0 = ax + bv.x, h1 = ay + bv.y;
    h0 = h0 > 0.f ? 2.f * h0 : 0.f;
    h1 = h1 > 0.f ? 2.f * h1 : 0.f;
    unsigned i0 = (unsigned)r0 * 64u + (unsigned)lane * 2u;
    unsigned m0 = tf_hash(i0);
    unsigned m1 = tf_hash(i0 + 1u);
    float2 o0;
    o0.x = (m0 & 0x80000000u) ? 0.f : h0;
    o0.y = (m1 & 0x80000000u) ? 0.f : h1;
    reinterpret_cast<float2*>(out)[(unsigned)r0 * 32u + lane] = o0;

    float g0 = bx + bv.x, g1 = by + bv.y;
    g0 = g0 > 0.f ? 2.f * g0 : 0.f;
    g1 = g1 > 0.f ? 2.f * g1 : 0.f;
    unsigned i1 = (unsigned)r1 * 64u + (unsigned)lane * 2u;
    unsigned n0 = tf_hash(i1);
    unsigned n1 = tf_hash(i1 + 1u);
    float2 o1;
    o1.x = (n0 & 0x80000000u) ? 0.f : g0;
    o1.y = (n1 & 0x80000000u) ? 0.f : g1;
    reinterpret_cast<float2*>(out)[(unsigned)r1 * 32u + lane] = o1;
}

// ---------------------------------------------------------------------------
extern "C" void kernel_launch(void* const* d_in, const int* in_sizes, int n_in,
                              void* d_out, int out_size) {
    const float* x    = (const float*)d_in[0];
    const int*   erow = (const int*)  d_in[1];
    const int*   ecol = (const int*)  d_in[2];
    const float* ev   = (const float*)d_in[3];
    const float* W    = (const float*)d_in[4];
    const float* b    = (const float*)d_in[5];
    float* out = (float*)d_out;

    build_kernel<<<6250, 256>>>(erow, ecol, ev);
    gemm_kernel <<<391, 256>>>(x, W);
    reduce_kernel<<<6250, 256>>>(out, b);
}